// round 1
// baseline (speedup 1.0000x reference)
#include <cuda_runtime.h>
#include <cstddef>

// Problem constants (fixed by setup_inputs)
#define R_DIM 256
#define C_DIM 256
#define E_DIM 768
#define H_HEADS 12
#define DH 64
#define TOK (R_DIM * C_DIM)          // 65536 tokens
#define SCALE 0.0078125f             // (Dh^-0.5)/sqrt(R) = (1/8)/16 = 1/128

// Scratch: Q, K, V, Ctx (each TOK*E) + scores W (H*C*C)
#define PROJ_ELEMS ((size_t)TOK * E_DIM)            // 50331648
#define W_ELEMS ((size_t)H_HEADS * C_DIM * C_DIM)   // 786432
__device__ float g_scratch[4 * PROJ_ELEMS + W_ELEMS];

// ---------------------------------------------------------------------------
// GEMM (NT): C[m,n] = alpha * ( sum_k A[m,k]*B[n,k] + bias[n] )
// A: [M,K] row-major, B: [N,K] row-major. M%128==0, N%128==0, K%8==0.
// 128x128 block, 256 threads, 8x8 micro-tile, BK=8.
// ---------------------------------------------------------------------------
__global__ __launch_bounds__(256) void gemm_nt_bias(
    const float* __restrict__ A, const float* __restrict__ B,
    const float* __restrict__ bias, float* __restrict__ C,
    int M, int N, int K, float alpha)
{
    __shared__ float As[8][128];
    __shared__ float Bs[8][128];

    const int tid = threadIdx.x;
    const int tx = tid & 15;         // 0..15
    const int ty = tid >> 4;         // 0..15
    const int m0 = blockIdx.y * 128;
    const int n0 = blockIdx.x * 128;

    const int lrow = tid >> 1;       // 0..127
    const int lk   = (tid & 1) * 4;  // 0 or 4

    const float* Ap = A + (size_t)(m0 + lrow) * K + lk;
    const float* Bp = B + (size_t)(n0 + lrow) * K + lk;

    float acc[8][8];
#pragma unroll
    for (int i = 0; i < 8; i++)
#pragma unroll
        for (int j = 0; j < 8; j++) acc[i][j] = 0.0f;

    for (int k0 = 0; k0 < K; k0 += 8) {
        float4 av = *(const float4*)(Ap + k0);
        float4 bv = *(const float4*)(Bp + k0);
        __syncthreads();
        As[lk + 0][lrow] = av.x; As[lk + 1][lrow] = av.y;
        As[lk + 2][lrow] = av.z; As[lk + 3][lrow] = av.w;
        Bs[lk + 0][lrow] = bv.x; Bs[lk + 1][lrow] = bv.y;
        Bs[lk + 2][lrow] = bv.z; Bs[lk + 3][lrow] = bv.w;
        __syncthreads();

#pragma unroll
        for (int kk = 0; kk < 8; kk++) {
            float a[8], b[8];
            *(float4*)&a[0] = *(const float4*)&As[kk][ty * 8];
            *(float4*)&a[4] = *(const float4*)&As[kk][ty * 8 + 4];
            *(float4*)&b[0] = *(const float4*)&Bs[kk][tx * 8];
            *(float4*)&b[4] = *(const float4*)&Bs[kk][tx * 8 + 4];
#pragma unroll
            for (int i = 0; i < 8; i++)
#pragma unroll
                for (int j = 0; j < 8; j++)
                    acc[i][j] += a[i] * b[j];
        }
    }

#pragma unroll
    for (int i = 0; i < 8; i++) {
        const int m = m0 + ty * 8 + i;
#pragma unroll
        for (int j = 0; j < 8; j++) {
            const int n = n0 + tx * 8 + j;
            C[(size_t)m * N + n] = alpha * (acc[i][j] + bias[n]);
        }
    }
}

// ---------------------------------------------------------------------------
// Scores: W[h,i,j] = sum_{r,d} Q[(r*256+i)*768 + h*64+d] * K[(r*256+j)*768 + h*64+d]
// grid = (4 i-tiles, 4 j-tiles, 12 heads), 64x64 tile, 256 threads, 4x4 micro.
// ---------------------------------------------------------------------------
__global__ __launch_bounds__(256) void scores_kernel(
    const float* __restrict__ Q, const float* __restrict__ Kmat,
    float* __restrict__ W)
{
    __shared__ float Qs[64][68];   // [d][i], padded
    __shared__ float Ks[64][68];   // [d][j], padded

    const int h  = blockIdx.z;
    const int i0 = blockIdx.x * 64;
    const int j0 = blockIdx.y * 64;
    const int tid = threadIdx.x;
    const int tx = tid & 15;
    const int ty = tid >> 4;

    float acc[4][4];
#pragma unroll
    for (int i = 0; i < 4; i++)
#pragma unroll
        for (int j = 0; j < 4; j++) acc[i][j] = 0.0f;

    for (int r = 0; r < R_DIM; r++) {
        const float* Qb = Q    + (size_t)(r * 256 + i0) * E_DIM + h * DH;
        const float* Kb = Kmat + (size_t)(r * 256 + j0) * E_DIM + h * DH;
        __syncthreads();
#pragma unroll
        for (int p = 0; p < 4; p++) {
            const int idx = tid * 4 + p * 1024;   // 0..4095
            const int row = idx >> 6;             // 0..63
            const int d   = idx & 63;             // multiple of 4
            float4 qv = *(const float4*)(Qb + row * E_DIM + d);
            float4 kv = *(const float4*)(Kb + row * E_DIM + d);
            Qs[d + 0][row] = qv.x; Qs[d + 1][row] = qv.y;
            Qs[d + 2][row] = qv.z; Qs[d + 3][row] = qv.w;
            Ks[d + 0][row] = kv.x; Ks[d + 1][row] = kv.y;
            Ks[d + 2][row] = kv.z; Ks[d + 3][row] = kv.w;
        }
        __syncthreads();

#pragma unroll 16
        for (int kk = 0; kk < 64; kk++) {
            float a[4], b[4];
            *(float4*)a = *(const float4*)&Qs[kk][ty * 4];
            *(float4*)b = *(const float4*)&Ks[kk][tx * 4];
#pragma unroll
            for (int i = 0; i < 4; i++)
#pragma unroll
                for (int j = 0; j < 4; j++)
                    acc[i][j] += a[i] * b[j];
        }
    }

#pragma unroll
    for (int i = 0; i < 4; i++)
#pragma unroll
        for (int j = 0; j < 4; j++)
            W[(size_t)h * 65536 + (size_t)(i0 + ty * 4 + i) * 256 + (j0 + tx * 4 + j)]
                = acc[i][j];
}

// ---------------------------------------------------------------------------
// Softmax over last axis: one block (256 threads) per (h,i) row of 256.
// ---------------------------------------------------------------------------
__global__ __launch_bounds__(256) void softmax_kernel(
    const float* __restrict__ W, float* __restrict__ P)
{
    __shared__ float red[8];
    const int row = blockIdx.x;          // h*256 + i, 0..3071
    const int tid = threadIdx.x;

    const float v = W[(size_t)row * 256 + tid];

    float m = v;
#pragma unroll
    for (int o = 16; o > 0; o >>= 1)
        m = fmaxf(m, __shfl_xor_sync(0xffffffffu, m, o));
    if ((tid & 31) == 0) red[tid >> 5] = m;
    __syncthreads();
    float m_all = red[0];
#pragma unroll
    for (int w = 1; w < 8; w++) m_all = fmaxf(m_all, red[w]);

    const float e = __expf(v - m_all);

    float s = e;
#pragma unroll
    for (int o = 16; o > 0; o >>= 1)
        s += __shfl_xor_sync(0xffffffffu, s, o);
    __syncthreads();                 // done reading red for max
    if ((tid & 31) == 0) red[tid >> 5] = s;
    __syncthreads();
    float s_all = 0.0f;
#pragma unroll
    for (int w = 0; w < 8; w++) s_all += red[w];

    P[(size_t)row * 256 + tid] = e / s_all;
}

// ---------------------------------------------------------------------------
// Context: Ctx[(r*256+i)*768 + h*64+d] = sum_j P[h,i,j] * V[(r*256+j)*768 + h*64+d]
// grid = (4 i-tiles, 256 r, 12 h). 64(i) x 64(d) tile, k = j in tiles of 32.
// ---------------------------------------------------------------------------
__global__ __launch_bounds__(256) void context_kernel(
    const float* __restrict__ P, const float* __restrict__ V,
    float* __restrict__ Ctx)
{
    __shared__ float Ps[32][68];   // [j][i]
    __shared__ float Vs[32][68];   // [j][d]

    const int h  = blockIdx.z;
    const int r  = blockIdx.y;
    const int i0 = blockIdx.x * 64;
    const int tid = threadIdx.x;
    const int tx = tid & 15;
    const int ty = tid >> 4;

    float acc[4][4];
#pragma unroll
    for (int i = 0; i < 4; i++)
#pragma unroll
        for (int j = 0; j < 4; j++) acc[i][j] = 0.0f;

    const float* Ph = P + (size_t)h * 65536;

    for (int j0 = 0; j0 < 256; j0 += 32) {
        __syncthreads();
#pragma unroll
        for (int p = 0; p < 2; p++) {
            const int idx = tid * 4 + p * 1024;   // 0..2047
            // P tile: 64 i x 32 j
            {
                const int i = idx >> 5;           // 0..63
                const int j = idx & 31;           // multiple of 4
                float4 pv = *(const float4*)(Ph + (size_t)(i0 + i) * 256 + j0 + j);
                Ps[j + 0][i] = pv.x; Ps[j + 1][i] = pv.y;
                Ps[j + 2][i] = pv.z; Ps[j + 3][i] = pv.w;
            }
            // V tile: 32 j x 64 d
            {
                const int jv = idx >> 6;          // 0..31
                const int d  = idx & 63;          // multiple of 4
                float4 vv = *(const float4*)(V + (size_t)(r * 256 + j0 + jv) * E_DIM
                                               + h * DH + d);
                *(float4*)&Vs[jv][d] = vv;
            }
        }
        __syncthreads();

#pragma unroll 16
        for (int kk = 0; kk < 32; kk++) {
            float a[4], b[4];
            *(float4*)a = *(const float4*)&Ps[kk][ty * 4];
            *(float4*)b = *(const float4*)&Vs[kk][tx * 4];
#pragma unroll
            for (int i = 0; i < 4; i++)
#pragma unroll
                for (int j = 0; j < 4; j++)
                    acc[i][j] += a[i] * b[j];
        }
    }

#pragma unroll
    for (int i = 0; i < 4; i++)
#pragma unroll
        for (int j = 0; j < 4; j++)
            Ctx[(size_t)(r * 256 + i0 + ty * 4 + i) * E_DIM + h * DH + tx * 4 + j]
                = acc[i][j];
}

// ---------------------------------------------------------------------------
// Launch
// ---------------------------------------------------------------------------
extern "C" void kernel_launch(void* const* d_in, const int* in_sizes, int n_in,
                              void* d_out, int out_size)
{
    const float* x  = (const float*)d_in[0];
    const float* Wq = (const float*)d_in[1];
    const float* bq = (const float*)d_in[2];
    const float* Wk = (const float*)d_in[3];
    const float* bk = (const float*)d_in[4];
    const float* Wv = (const float*)d_in[5];
    const float* bv = (const float*)d_in[6];
    const float* Wo = (const float*)d_in[7];
    const float* bo = (const float*)d_in[8];

    float* out   = (float*)d_out;
    float* out_y = out;                          // (R,C,B,E)
    float* out_p = out + PROJ_ELEMS;             // (H,B,C,C)

    float* base = nullptr;
    cudaGetSymbolAddress((void**)&base, g_scratch);
    float* Qb   = base;
    float* Kb   = base + PROJ_ELEMS;
    float* Vb   = base + 2 * PROJ_ELEMS;
    float* Ctxb = base + 3 * PROJ_ELEMS;
    float* Wb   = base + 4 * PROJ_ELEMS;

    dim3 gproj(E_DIM / 128, TOK / 128);          // (6, 512)

    gemm_nt_bias<<<gproj, 256>>>(x, Wq, bq, Qb, TOK, E_DIM, E_DIM, SCALE);
    gemm_nt_bias<<<gproj, 256>>>(x, Wk, bk, Kb, TOK, E_DIM, E_DIM, 1.0f);
    gemm_nt_bias<<<gproj, 256>>>(x, Wv, bv, Vb, TOK, E_DIM, E_DIM, 1.0f);

    scores_kernel<<<dim3(4, 4, H_HEADS), 256>>>(Qb, Kb, Wb);
    softmax_kernel<<<H_HEADS * C_DIM, 256>>>(Wb, out_p);
    context_kernel<<<dim3(4, R_DIM, H_HEADS), 256>>>(out_p, Vb, Ctxb);

    gemm_nt_bias<<<gproj, 256>>>(Ctxb, Wo, bo, out_y, TOK, E_DIM, E_DIM, 1.0f);
}

// round 2
// speedup vs baseline: 1.0007x; 1.0007x over previous
#include <cuda_runtime.h>
#include <cstddef>

// Problem constants (fixed by setup_inputs)
#define R_DIM 256
#define C_DIM 256
#define E_DIM 768
#define H_HEADS 12
#define DH 64
#define TOK (R_DIM * C_DIM)          // 65536 tokens
#define SCALE 0.0078125f             // (Dh^-0.5)/sqrt(R) = (1/8)/16 = 1/128

// Scratch: Q, K, V, Ctx (each TOK*E) + scores W (H*C*C)
#define PROJ_ELEMS ((size_t)TOK * E_DIM)            // 50331648
#define W_ELEMS ((size_t)H_HEADS * C_DIM * C_DIM)   // 786432
__device__ float g_scratch[4 * PROJ_ELEMS + W_ELEMS];

// ---------------------------------------------------------------------------
// GEMM (NT): C[m,n] = alpha * ( sum_k A[m,k]*B[n,k] + bias[n] )
// A: [M,K] row-major, B: [N,K] row-major. M%128==0, N%128==0, K%8==0.
// 128x128 block, 256 threads, 8x8 micro-tile, BK=8.
// ---------------------------------------------------------------------------
__global__ __launch_bounds__(256) void gemm_nt_bias(
    const float* __restrict__ A, const float* __restrict__ B,
    const float* __restrict__ bias, float* __restrict__ C,
    int M, int N, int K, float alpha)
{
    __shared__ float As[8][128];
    __shared__ float Bs[8][128];

    const int tid = threadIdx.x;
    const int tx = tid & 15;         // 0..15
    const int ty = tid >> 4;         // 0..15
    const int m0 = blockIdx.y * 128;
    const int n0 = blockIdx.x * 128;

    const int lrow = tid >> 1;       // 0..127
    const int lk   = (tid & 1) * 4;  // 0 or 4

    const float* Ap = A + (size_t)(m0 + lrow) * K + lk;
    const float* Bp = B + (size_t)(n0 + lrow) * K + lk;

    float acc[8][8];
#pragma unroll
    for (int i = 0; i < 8; i++)
#pragma unroll
        for (int j = 0; j < 8; j++) acc[i][j] = 0.0f;

    for (int k0 = 0; k0 < K; k0 += 8) {
        float4 av = *(const float4*)(Ap + k0);
        float4 bv = *(const float4*)(Bp + k0);
        __syncthreads();
        As[lk + 0][lrow] = av.x; As[lk + 1][lrow] = av.y;
        As[lk + 2][lrow] = av.z; As[lk + 3][lrow] = av.w;
        Bs[lk + 0][lrow] = bv.x; Bs[lk + 1][lrow] = bv.y;
        Bs[lk + 2][lrow] = bv.z; Bs[lk + 3][lrow] = bv.w;
        __syncthreads();

#pragma unroll
        for (int kk = 0; kk < 8; kk++) {
            float a[8], b[8];
            *(float4*)&a[0] = *(const float4*)&As[kk][ty * 8];
            *(float4*)&a[4] = *(const float4*)&As[kk][ty * 8 + 4];
            *(float4*)&b[0] = *(const float4*)&Bs[kk][tx * 8];
            *(float4*)&b[4] = *(const float4*)&Bs[kk][tx * 8 + 4];
#pragma unroll
            for (int i = 0; i < 8; i++)
#pragma unroll
                for (int j = 0; j < 8; j++)
                    acc[i][j] += a[i] * b[j];
        }
    }

#pragma unroll
    for (int i = 0; i < 8; i++) {
        const int m = m0 + ty * 8 + i;
#pragma unroll
        for (int j = 0; j < 8; j++) {
            const int n = n0 + tx * 8 + j;
            C[(size_t)m * N + n] = alpha * (acc[i][j] + bias[n]);
        }
    }
}

// ---------------------------------------------------------------------------
// Scores: W[h,i,j] = sum_{r,d} Q[(r*256+i)*768 + h*64+d] * K[(r*256+j)*768 + h*64+d]
// grid = (4 i-tiles, 4 j-tiles, 12 heads), 64x64 tile, 256 threads, 4x4 micro.
// ---------------------------------------------------------------------------
__global__ __launch_bounds__(256) void scores_kernel(
    const float* __restrict__ Q, const float* __restrict__ Kmat,
    float* __restrict__ W)
{
    __shared__ float Qs[64][68];   // [d][i], padded
    __shared__ float Ks[64][68];   // [d][j], padded

    const int h  = blockIdx.z;
    const int i0 = blockIdx.x * 64;
    const int j0 = blockIdx.y * 64;
    const int tid = threadIdx.x;
    const int tx = tid & 15;
    const int ty = tid >> 4;

    float acc[4][4];
#pragma unroll
    for (int i = 0; i < 4; i++)
#pragma unroll
        for (int j = 0; j < 4; j++) acc[i][j] = 0.0f;

    for (int r = 0; r < R_DIM; r++) {
        const float* Qb = Q    + (size_t)(r * 256 + i0) * E_DIM + h * DH;
        const float* Kb = Kmat + (size_t)(r * 256 + j0) * E_DIM + h * DH;
        __syncthreads();
#pragma unroll
        for (int p = 0; p < 4; p++) {
            const int idx = tid * 4 + p * 1024;   // 0..4095
            const int row = idx >> 6;             // 0..63
            const int d   = idx & 63;             // multiple of 4
            float4 qv = *(const float4*)(Qb + row * E_DIM + d);
            float4 kv = *(const float4*)(Kb + row * E_DIM + d);
            Qs[d + 0][row] = qv.x; Qs[d + 1][row] = qv.y;
            Qs[d + 2][row] = qv.z; Qs[d + 3][row] = qv.w;
            Ks[d + 0][row] = kv.x; Ks[d + 1][row] = kv.y;
            Ks[d + 2][row] = kv.z; Ks[d + 3][row] = kv.w;
        }
        __syncthreads();

#pragma unroll 16
        for (int kk = 0; kk < 64; kk++) {
            float a[4], b[4];
            *(float4*)a = *(const float4*)&Qs[kk][ty * 4];
            *(float4*)b = *(const float4*)&Ks[kk][tx * 4];
#pragma unroll
            for (int i = 0; i < 4; i++)
#pragma unroll
                for (int j = 0; j < 4; j++)
                    acc[i][j] += a[i] * b[j];
        }
    }

#pragma unroll
    for (int i = 0; i < 4; i++)
#pragma unroll
        for (int j = 0; j < 4; j++)
            W[(size_t)h * 65536 + (size_t)(i0 + ty * 4 + i) * 256 + (j0 + tx * 4 + j)]
                = acc[i][j];
}

// ---------------------------------------------------------------------------
// Softmax over last axis: one block (256 threads) per (h,i) row of 256.
// ---------------------------------------------------------------------------
__global__ __launch_bounds__(256) void softmax_kernel(
    const float* __restrict__ W, float* __restrict__ P)
{
    __shared__ float red[8];
    const int row = blockIdx.x;          // h*256 + i, 0..3071
    const int tid = threadIdx.x;

    const float v = W[(size_t)row * 256 + tid];

    float m = v;
#pragma unroll
    for (int o = 16; o > 0; o >>= 1)
        m = fmaxf(m, __shfl_xor_sync(0xffffffffu, m, o));
    if ((tid & 31) == 0) red[tid >> 5] = m;
    __syncthreads();
    float m_all = red[0];
#pragma unroll
    for (int w = 1; w < 8; w++) m_all = fmaxf(m_all, red[w]);

    const float e = __expf(v - m_all);

    float s = e;
#pragma unroll
    for (int o = 16; o > 0; o >>= 1)
        s += __shfl_xor_sync(0xffffffffu, s, o);
    __syncthreads();                 // done reading red for max
    if ((tid & 31) == 0) red[tid >> 5] = s;
    __syncthreads();
    float s_all = 0.0f;
#pragma unroll
    for (int w = 0; w < 8; w++) s_all += red[w];

    P[(size_t)row * 256 + tid] = e / s_all;
}

// ---------------------------------------------------------------------------
// Context: Ctx[(r*256+i)*768 + h*64+d] = sum_j P[h,i,j] * V[(r*256+j)*768 + h*64+d]
// grid = (4 i-tiles, 256 r, 12 h). 64(i) x 64(d) tile, k = j in tiles of 32.
// ---------------------------------------------------------------------------
__global__ __launch_bounds__(256) void context_kernel(
    const float* __restrict__ P, const float* __restrict__ V,
    float* __restrict__ Ctx)
{
    __shared__ float Ps[32][68];   // [j][i]
    __shared__ float Vs[32][68];   // [j][d]

    const int h  = blockIdx.z;
    const int r  = blockIdx.y;
    const int i0 = blockIdx.x * 64;
    const int tid = threadIdx.x;
    const int tx = tid & 15;
    const int ty = tid >> 4;

    float acc[4][4];
#pragma unroll
    for (int i = 0; i < 4; i++)
#pragma unroll
        for (int j = 0; j < 4; j++) acc[i][j] = 0.0f;

    const float* Ph = P + (size_t)h * 65536;

    for (int j0 = 0; j0 < 256; j0 += 32) {
        __syncthreads();
#pragma unroll
        for (int p = 0; p < 2; p++) {
            const int idx = tid * 4 + p * 1024;   // 0..2047
            // P tile: 64 i x 32 j
            {
                const int i = idx >> 5;           // 0..63
                const int j = idx & 31;           // multiple of 4
                float4 pv = *(const float4*)(Ph + (size_t)(i0 + i) * 256 + j0 + j);
                Ps[j + 0][i] = pv.x; Ps[j + 1][i] = pv.y;
                Ps[j + 2][i] = pv.z; Ps[j + 3][i] = pv.w;
            }
            // V tile: 32 j x 64 d
            {
                const int jv = idx >> 6;          // 0..31
                const int d  = idx & 63;          // multiple of 4
                float4 vv = *(const float4*)(V + (size_t)(r * 256 + j0 + jv) * E_DIM
                                               + h * DH + d);
                *(float4*)&Vs[jv][d] = vv;
            }
        }
        __syncthreads();

#pragma unroll 16
        for (int kk = 0; kk < 32; kk++) {
            float a[4], b[4];
            *(float4*)a = *(const float4*)&Ps[kk][ty * 4];
            *(float4*)b = *(const float4*)&Vs[kk][tx * 4];
#pragma unroll
            for (int i = 0; i < 4; i++)
#pragma unroll
                for (int j = 0; j < 4; j++)
                    acc[i][j] += a[i] * b[j];
        }
    }

#pragma unroll
    for (int i = 0; i < 4; i++)
#pragma unroll
        for (int j = 0; j < 4; j++)
            Ctx[(size_t)(r * 256 + i0 + ty * 4 + i) * E_DIM + h * DH + tx * 4 + j]
                = acc[i][j];
}

// ---------------------------------------------------------------------------
// Launch
// ---------------------------------------------------------------------------
extern "C" void kernel_launch(void* const* d_in, const int* in_sizes, int n_in,
                              void* d_out, int out_size)
{
    const float* x  = (const float*)d_in[0];
    const float* Wq = (const float*)d_in[1];
    const float* bq = (const float*)d_in[2];
    const float* Wk = (const float*)d_in[3];
    const float* bk = (const float*)d_in[4];
    const float* Wv = (const float*)d_in[5];
    const float* bv = (const float*)d_in[6];
    const float* Wo = (const float*)d_in[7];
    const float* bo = (const float*)d_in[8];

    float* out   = (float*)d_out;
    float* out_y = out;                          // (R,C,B,E)
    float* out_p = out + PROJ_ELEMS;             // (H,B,C,C)

    float* base = nullptr;
    cudaGetSymbolAddress((void**)&base, g_scratch);
    float* Qb   = base;
    float* Kb   = base + PROJ_ELEMS;
    float* Vb   = base + 2 * PROJ_ELEMS;
    float* Ctxb = base + 3 * PROJ_ELEMS;
    float* Wb   = base + 4 * PROJ_ELEMS;

    dim3 gproj(E_DIM / 128, TOK / 128);          // (6, 512)

    gemm_nt_bias<<<gproj, 256>>>(x, Wq, bq, Qb, TOK, E_DIM, E_DIM, SCALE);
    gemm_nt_bias<<<gproj, 256>>>(x, Wk, bk, Kb, TOK, E_DIM, E_DIM, 1.0f);
    gemm_nt_bias<<<gproj, 256>>>(x, Wv, bv, Vb, TOK, E_DIM, E_DIM, 1.0f);

    scores_kernel<<<dim3(4, 4, H_HEADS), 256>>>(Qb, Kb, Wb);
    softmax_kernel<<<H_HEADS * C_DIM, 256>>>(Wb, out_p);
    context_kernel<<<dim3(4, R_DIM, H_HEADS), 256>>>(out_p, Vb, Ctxb);

    gemm_nt_bias<<<gproj, 256>>>(Ctxb, Wo, bo, out_y, TOK, E_DIM, E_DIM, 1.0f);
}

// round 4
// speedup vs baseline: 1.9729x; 1.9714x over previous
#include <cuda_runtime.h>
#include <cuda_bf16.h>
#include <cstdint>
#include <cstddef>

#define R_DIM 256
#define C_DIM 256
#define E_DIM 768
#define H_HEADS 12
#define DH 64
#define TOK (R_DIM * C_DIM)
#define SCALE 0.0078125f
#define KDIM 768

#define PROJ_ELEMS ((size_t)TOK * E_DIM)
#define W_ELEMS ((size_t)H_HEADS * C_DIM * C_DIM)
#define WSZ ((size_t)E_DIM * E_DIM)

__device__ float g_f32[4 * PROJ_ELEMS + W_ELEMS];
__device__ __nv_bfloat16 g_Ah[PROJ_ELEMS];
__device__ __nv_bfloat16 g_Al[PROJ_ELEMS];
__device__ __nv_bfloat16 g_Wh[4 * WSZ];
__device__ __nv_bfloat16 g_Wl[4 * WSZ];

// ---------------- helpers ----------------
__device__ __forceinline__ uint32_t smem_u32(const void* p) {
    uint32_t a;
    asm("{ .reg .u64 t; cvta.to.shared.u64 t, %1; cvt.u32.u64 %0, t; }" : "=r"(a) : "l"(p));
    return a;
}
__device__ __forceinline__ void cp16(uint32_t dst, const void* src) {
    asm volatile("cp.async.cg.shared.global [%0], [%1], 16;\n" :: "r"(dst), "l"(src));
}
__device__ __forceinline__ void hmma(float* c, const uint32_t* a, const uint32_t* b) {
    asm volatile(
        "mma.sync.aligned.m16n8k16.row.col.f32.bf16.bf16.f32 "
        "{%0,%1,%2,%3}, {%4,%5,%6,%7}, {%8,%9}, {%0,%1,%2,%3};"
        : "+f"(c[0]), "+f"(c[1]), "+f"(c[2]), "+f"(c[3])
        : "r"(a[0]), "r"(a[1]), "r"(a[2]), "r"(a[3]), "r"(b[0]), "r"(b[1]));
}

// ---------------- split fp32 -> bf16 hi/lo ----------------
__global__ __launch_bounds__(256) void split_kernel(
    const float* __restrict__ src, __nv_bfloat16* __restrict__ hi,
    __nv_bfloat16* __restrict__ lo, int n)
{
    int i = (blockIdx.x * 256 + threadIdx.x) * 4;
    if (i >= n) return;
    float4 v = *(const float4*)(src + i);
    float f[4] = {v.x, v.y, v.z, v.w};
    unsigned short h[4], l[4];
#pragma unroll
    for (int k = 0; k < 4; k++) {
        __nv_bfloat16 hb = __float2bfloat16_rn(f[k]);
        __nv_bfloat16 lb = __float2bfloat16_rn(f[k] - __bfloat162float(hb));
        h[k] = *(unsigned short*)&hb; l[k] = *(unsigned short*)&lb;
    }
    uint2 hp, lp;
    hp.x = h[0] | ((uint32_t)h[1] << 16); hp.y = h[2] | ((uint32_t)h[3] << 16);
    lp.x = l[0] | ((uint32_t)l[1] << 16); lp.y = l[2] | ((uint32_t)l[3] << 16);
    *(uint2*)(hi + i) = hp; *(uint2*)(lo + i) = lp;
}

// ---------------------------------------------------------------------------
// HMMA GEMM (NT, bf16x3): C[m,n] = alpha*(sum_k A[m,k]B[n,k] + bias[n])
// M = grid.y*128, N = grid.x*128 (N=768), K=768.
// CTA 128x128, 8 warps (2m x 4n), warp tile 64x32, BK=32, 2-stage cp.async.
// Smem tiles: rows of 64B (32 bf16), granule-XOR swizzle: conflict-free LDS.
// ---------------------------------------------------------------------------
#define BK32 32
#define NCH (KDIM / BK32)              // 24
#define TILE_B 8192                    // 128 rows * 64 B
#define ST_AH 0
#define ST_AL 8192
#define ST_BH 16384
#define ST_BL 24576
#define STAGE 32768
#define GEMM_SMEM (2 * STAGE)          // 65536

extern __shared__ char dynsmem[];

// physical byte offset of (row, kbyte) inside a 128x64B tile
__device__ __forceinline__ uint32_t swz(int row, int kbyte) {
    int g = kbyte >> 4, rem = kbyte & 15;
    int pg = g ^ ((row >> 1) & 3);
    return (uint32_t)(row * 64 + pg * 16 + rem);
}

__global__ __launch_bounds__(256, 1) void gemm_hmma(
    const __nv_bfloat16* __restrict__ Ah, const __nv_bfloat16* __restrict__ Al,
    const __nv_bfloat16* __restrict__ Bh, const __nv_bfloat16* __restrict__ Bl,
    const float* __restrict__ bias, float* __restrict__ C, float alpha)
{
    char* sm = dynsmem;
    const uint32_t sb = smem_u32(sm);
    const int tid = threadIdx.x;
    const int wid = tid >> 5, lane = tid & 31;
    const int gid = lane >> 2, tig = lane & 3;
    const int wm = (wid & 1) * 64;        // warp m offset in CTA tile
    const int wn = (wid >> 1) * 32;       // warp n offset
    const int m0 = blockIdx.y * 128;
    const int n0 = blockIdx.x * 128;

    float acc[4][4][4];
#pragma unroll
    for (int mt = 0; mt < 4; mt++)
#pragma unroll
        for (int nt = 0; nt < 4; nt++)
#pragma unroll
            for (int e = 0; e < 4; e++) acc[mt][nt][e] = 0.0f;

    // each thread copies 8 x 16B granules per chunk (2048 granules total)
    auto load_chunk = [&](int c) {
        const uint32_t stg = sb + (uint32_t)(c & 1) * STAGE;
        const int k0 = c * BK32;
#pragma unroll
        for (int t = 0; t < 8; t++) {
            int task = tid + t * 256;            // 0..2047
            int isB = task >> 10;                // 0:A 1:B
            int rem = task & 1023;
            int s = rem >> 9;                    // 0:hi 1:lo
            int r2 = rem & 511;
            int row = r2 >> 2, g = r2 & 3;
            const __nv_bfloat16* src;
            uint32_t dst;
            if (!isB) {
                src = (s ? Al : Ah) + (size_t)(m0 + row) * KDIM + k0 + g * 8;
                dst = stg + (s ? ST_AL : ST_AH) + swz(row, g * 16);
            } else {
                src = (s ? Bl : Bh) + (size_t)(n0 + row) * KDIM + k0 + g * 8;
                dst = stg + (s ? ST_BL : ST_BH) + swz(row, g * 16);
            }
            cp16(dst, src);
        }
        asm volatile("cp.async.commit_group;\n" ::: "memory");
    };

    load_chunk(0);
    load_chunk(1);

    for (int c = 0; c < NCH; c++) {
        const uint32_t stg_off = (uint32_t)(c & 1) * STAGE;
        const char* Abase = sm + stg_off;
        const char* Bbase = sm + stg_off;
        if (c == NCH - 1) asm volatile("cp.async.wait_group 0;\n" ::: "memory");
        else              asm volatile("cp.async.wait_group 1;\n" ::: "memory");
        __syncthreads();

#pragma unroll
        for (int ks = 0; ks < 2; ks++) {
            const int kb = ks * 32;
            uint32_t a[4][4], b[4][2], b2[4][2];
            // A hi fragments
#pragma unroll
            for (int mt = 0; mt < 4; mt++) {
                int row = wm + mt * 16 + gid;
                a[mt][0] = *(const uint32_t*)(Abase + ST_AH + swz(row,     kb + tig * 4));
                a[mt][1] = *(const uint32_t*)(Abase + ST_AH + swz(row + 8, kb + tig * 4));
                a[mt][2] = *(const uint32_t*)(Abase + ST_AH + swz(row,     kb + tig * 4 + 16));
                a[mt][3] = *(const uint32_t*)(Abase + ST_AH + swz(row + 8, kb + tig * 4 + 16));
            }
            // B hi fragments
#pragma unroll
            for (int nt = 0; nt < 4; nt++) {
                int row = wn + nt * 8 + gid;
                b[nt][0] = *(const uint32_t*)(Bbase + ST_BH + swz(row, kb + tig * 4));
                b[nt][1] = *(const uint32_t*)(Bbase + ST_BH + swz(row, kb + tig * 4 + 16));
            }
#pragma unroll
            for (int mt = 0; mt < 4; mt++)
#pragma unroll
                for (int nt = 0; nt < 4; nt++) hmma(acc[mt][nt], a[mt], b[nt]);
            // B lo
#pragma unroll
            for (int nt = 0; nt < 4; nt++) {
                int row = wn + nt * 8 + gid;
                b2[nt][0] = *(const uint32_t*)(Bbase + ST_BL + swz(row, kb + tig * 4));
                b2[nt][1] = *(const uint32_t*)(Bbase + ST_BL + swz(row, kb + tig * 4 + 16));
            }
#pragma unroll
            for (int mt = 0; mt < 4; mt++)
#pragma unroll
                for (int nt = 0; nt < 4; nt++) hmma(acc[mt][nt], a[mt], b2[nt]);
            // A lo (overwrite a), with B hi
#pragma unroll
            for (int mt = 0; mt < 4; mt++) {
                int row = wm + mt * 16 + gid;
                a[mt][0] = *(const uint32_t*)(Abase + ST_AL + swz(row,     kb + tig * 4));
                a[mt][1] = *(const uint32_t*)(Abase + ST_AL + swz(row + 8, kb + tig * 4));
                a[mt][2] = *(const uint32_t*)(Abase + ST_AL + swz(row,     kb + tig * 4 + 16));
                a[mt][3] = *(const uint32_t*)(Abase + ST_AL + swz(row + 8, kb + tig * 4 + 16));
            }
#pragma unroll
            for (int mt = 0; mt < 4; mt++)
#pragma unroll
                for (int nt = 0; nt < 4; nt++) hmma(acc[mt][nt], a[mt], b[nt]);
        }
        __syncthreads();
        if (c + 2 < NCH) load_chunk(c + 2);
    }

    // epilogue
#pragma unroll
    for (int mt = 0; mt < 4; mt++) {
        const int row = m0 + wm + mt * 16 + gid;
#pragma unroll
        for (int nt = 0; nt < 4; nt++) {
            const int col = n0 + wn + nt * 8 + tig * 2;
            const float bb0 = __ldg(bias + col), bb1 = __ldg(bias + col + 1);
            float2 v0, v1;
            v0.x = alpha * (acc[mt][nt][0] + bb0);
            v0.y = alpha * (acc[mt][nt][1] + bb1);
            v1.x = alpha * (acc[mt][nt][2] + bb0);
            v1.y = alpha * (acc[mt][nt][3] + bb1);
            *(float2*)(C + (size_t)row * E_DIM + col) = v0;
            *(float2*)(C + (size_t)(row + 8) * E_DIM + col) = v1;
        }
    }
}

// ---------------- fp32 attention kernels (unchanged, proven) ----------------
__global__ __launch_bounds__(256) void scores_kernel(
    const float* __restrict__ Q, const float* __restrict__ Kmat, float* __restrict__ W)
{
    __shared__ float Qs[64][68];
    __shared__ float Ks[64][68];
    const int h = blockIdx.z, i0 = blockIdx.x * 64, j0 = blockIdx.y * 64;
    const int tid = threadIdx.x, tx = tid & 15, ty = tid >> 4;
    float acc[4][4];
#pragma unroll
    for (int i = 0; i < 4; i++)
#pragma unroll
        for (int j = 0; j < 4; j++) acc[i][j] = 0.0f;
    for (int r = 0; r < R_DIM; r++) {
        const float* Qb = Q    + (size_t)(r * 256 + i0) * E_DIM + h * DH;
        const float* Kb = Kmat + (size_t)(r * 256 + j0) * E_DIM + h * DH;
        __syncthreads();
#pragma unroll
        for (int p = 0; p < 4; p++) {
            const int idx = tid * 4 + p * 1024;
            const int row = idx >> 6, d = idx & 63;
            float4 qv = *(const float4*)(Qb + row * E_DIM + d);
            float4 kv = *(const float4*)(Kb + row * E_DIM + d);
            Qs[d+0][row]=qv.x; Qs[d+1][row]=qv.y; Qs[d+2][row]=qv.z; Qs[d+3][row]=qv.w;
            Ks[d+0][row]=kv.x; Ks[d+1][row]=kv.y; Ks[d+2][row]=kv.z; Ks[d+3][row]=kv.w;
        }
        __syncthreads();
#pragma unroll 16
        for (int kk = 0; kk < 64; kk++) {
            float a[4], b[4];
            *(float4*)a = *(const float4*)&Qs[kk][ty * 4];
            *(float4*)b = *(const float4*)&Ks[kk][tx * 4];
#pragma unroll
            for (int i = 0; i < 4; i++)
#pragma unroll
                for (int j = 0; j < 4; j++) acc[i][j] += a[i] * b[j];
        }
    }
#pragma unroll
    for (int i = 0; i < 4; i++)
#pragma unroll
        for (int j = 0; j < 4; j++)
            W[(size_t)h * 65536 + (size_t)(i0 + ty*4 + i) * 256 + (j0 + tx*4 + j)] = acc[i][j];
}

__global__ __launch_bounds__(256) void softmax_kernel(
    const float* __restrict__ W, float* __restrict__ P)
{
    __shared__ float red[8];
    const int row = blockIdx.x, tid = threadIdx.x;
    const float v = W[(size_t)row * 256 + tid];
    float m = v;
#pragma unroll
    for (int o = 16; o > 0; o >>= 1) m = fmaxf(m, __shfl_xor_sync(0xffffffffu, m, o));
    if ((tid & 31) == 0) red[tid >> 5] = m;
    __syncthreads();
    float m_all = red[0];
#pragma unroll
    for (int w = 1; w < 8; w++) m_all = fmaxf(m_all, red[w]);
    const float e = __expf(v - m_all);
    float s = e;
#pragma unroll
    for (int o = 16; o > 0; o >>= 1) s += __shfl_xor_sync(0xffffffffu, s, o);
    __syncthreads();
    if ((tid & 31) == 0) red[tid >> 5] = s;
    __syncthreads();
    float s_all = 0.0f;
#pragma unroll
    for (int w = 0; w < 8; w++) s_all += red[w];
    P[(size_t)row * 256 + tid] = e / s_all;
}

__global__ __launch_bounds__(256) void context_kernel(
    const float* __restrict__ P, const float* __restrict__ V, float* __restrict__ Ctx)
{
    __shared__ float Ps[32][68];
    __shared__ float Vs[32][68];
    const int h = blockIdx.z, r = blockIdx.y, i0 = blockIdx.x * 64;
    const int tid = threadIdx.x, tx = tid & 15, ty = tid >> 4;
    float acc[4][4];
#pragma unroll
    for (int i = 0; i < 4; i++)
#pragma unroll
        for (int j = 0; j < 4; j++) acc[i][j] = 0.0f;
    const float* Ph = P + (size_t)h * 65536;
    for (int j0 = 0; j0 < 256; j0 += 32) {
        __syncthreads();
#pragma unroll
        for (int p = 0; p < 2; p++) {
            const int idx = tid * 4 + p * 1024;
            {
                const int i = idx >> 5, j = idx & 31;
                float4 pv = *(const float4*)(Ph + (size_t)(i0 + i) * 256 + j0 + j);
                Ps[j+0][i]=pv.x; Ps[j+1][i]=pv.y; Ps[j+2][i]=pv.z; Ps[j+3][i]=pv.w;
            }
            {
                const int jv = idx >> 6, d = idx & 63;
                *(float4*)&Vs[jv][d] =
                    *(const float4*)(V + (size_t)(r * 256 + j0 + jv) * E_DIM + h * DH + d);
            }
        }
        __syncthreads();
#pragma unroll 16
        for (int kk = 0; kk < 32; kk++) {
            float a[4], b[4];
            *(float4*)a = *(const float4*)&Ps[kk][ty * 4];
            *(float4*)b = *(const float4*)&Vs[kk][tx * 4];
#pragma unroll
            for (int i = 0; i < 4; i++)
#pragma unroll
                for (int j = 0; j < 4; j++) acc[i][j] += a[i] * b[j];
        }
    }
#pragma unroll
    for (int i = 0; i < 4; i++)
#pragma unroll
        for (int j = 0; j < 4; j++)
            Ctx[(size_t)(r * 256 + i0 + ty*4 + i) * E_DIM + h * DH + tx*4 + j] = acc[i][j];
}

// ---------------- launch ----------------
extern "C" void kernel_launch(void* const* d_in, const int* in_sizes, int n_in,
                              void* d_out, int out_size)
{
    const float* x  = (const float*)d_in[0];
    const float* Wq = (const float*)d_in[1];
    const float* bq = (const float*)d_in[2];
    const float* Wk = (const float*)d_in[3];
    const float* bk = (const float*)d_in[4];
    const float* Wv = (const float*)d_in[5];
    const float* bv = (const float*)d_in[6];
    const float* Wo = (const float*)d_in[7];
    const float* bo = (const float*)d_in[8];

    float* out_y = (float*)d_out;
    float* out_p = (float*)d_out + PROJ_ELEMS;

    float* base = nullptr;
    cudaGetSymbolAddress((void**)&base, g_f32);
    float* Qb   = base;
    float* Kb   = base + PROJ_ELEMS;
    float* Vb   = base + 2 * PROJ_ELEMS;
    float* Ctxb = base + 3 * PROJ_ELEMS;
    float* Wsc  = base + 4 * PROJ_ELEMS;

    __nv_bfloat16 *Ah, *Al, *Wh, *Wl;
    cudaGetSymbolAddress((void**)&Ah, g_Ah);
    cudaGetSymbolAddress((void**)&Al, g_Al);
    cudaGetSymbolAddress((void**)&Wh, g_Wh);
    cudaGetSymbolAddress((void**)&Wl, g_Wl);

    cudaFuncSetAttribute(gemm_hmma, cudaFuncAttributeMaxDynamicSharedMemorySize, GEMM_SMEM);

    const int nx = (int)PROJ_ELEMS, nw = (int)WSZ;
    split_kernel<<<nx / 1024, 256>>>(x, Ah, Al, nx);
    split_kernel<<<nw / 1024, 256>>>(Wq, Wh + 0 * WSZ, Wl + 0 * WSZ, nw);
    split_kernel<<<nw / 1024, 256>>>(Wk, Wh + 1 * WSZ, Wl + 1 * WSZ, nw);
    split_kernel<<<nw / 1024, 256>>>(Wv, Wh + 2 * WSZ, Wl + 2 * WSZ, nw);
    split_kernel<<<nw / 1024, 256>>>(Wo, Wh + 3 * WSZ, Wl + 3 * WSZ, nw);

    dim3 gg(E_DIM / 128, TOK / 128);   // (6, 512)
    gemm_hmma<<<gg, 256, GEMM_SMEM>>>(Ah, Al, Wh + 0 * WSZ, Wl + 0 * WSZ, bq, Qb, SCALE);
    gemm_hmma<<<gg, 256, GEMM_SMEM>>>(Ah, Al, Wh + 1 * WSZ, Wl + 1 * WSZ, bk, Kb, 1.0f);
    gemm_hmma<<<gg, 256, GEMM_SMEM>>>(Ah, Al, Wh + 2 * WSZ, Wl + 2 * WSZ, bv, Vb, 1.0f);

    scores_kernel<<<dim3(4, 4, H_HEADS), 256>>>(Qb, Kb, Wsc);
    softmax_kernel<<<H_HEADS * C_DIM, 256>>>(Wsc, out_p);
    context_kernel<<<dim3(4, R_DIM, H_HEADS), 256>>>(out_p, Vb, Ctxb);

    split_kernel<<<nx / 1024, 256>>>(Ctxb, Ah, Al, nx);
    gemm_hmma<<<gg, 256, GEMM_SMEM>>>(Ah, Al, Wh + 3 * WSZ, Wl + 3 * WSZ, bo, out_y, 1.0f);
}

// round 5
// speedup vs baseline: 2.9628x; 1.5018x over previous
#include <cuda_runtime.h>
#include <cuda_bf16.h>
#include <cstdint>
#include <cstddef>

#define R_DIM 256
#define C_DIM 256
#define E_DIM 768
#define H_HEADS 12
#define DH 64
#define TOK (R_DIM * C_DIM)
#define SCALE 0.0078125f
#define KDIM 768

#define PROJ_ELEMS ((size_t)TOK * E_DIM)
#define W_ELEMS ((size_t)H_HEADS * C_DIM * C_DIM)
#define WSZ ((size_t)E_DIM * E_DIM)

__device__ __nv_bfloat16 g_Ah[PROJ_ELEMS];   // x split; later reused for Ctx split
__device__ __nv_bfloat16 g_Al[PROJ_ELEMS];
__device__ __nv_bfloat16 g_Qh[PROJ_ELEMS];
__device__ __nv_bfloat16 g_Ql[PROJ_ELEMS];
__device__ __nv_bfloat16 g_Kh[PROJ_ELEMS];
__device__ __nv_bfloat16 g_Kl[PROJ_ELEMS];
__device__ __nv_bfloat16 g_Vh[PROJ_ELEMS];
__device__ __nv_bfloat16 g_Vl[PROJ_ELEMS];
__device__ __nv_bfloat16 g_Wh[4 * WSZ];
__device__ __nv_bfloat16 g_Wl[4 * WSZ];
__device__ __nv_bfloat16 g_Ph[W_ELEMS];
__device__ __nv_bfloat16 g_Pl[W_ELEMS];
__device__ float g_Wpart[96 * 65536];        // 8 split-r partials x 12 heads x 256 x 256

extern __shared__ char dynsmem[];

// ---------------- helpers ----------------
__device__ __forceinline__ uint32_t smem_u32(const void* p) {
    uint32_t a;
    asm("{ .reg .u64 t; cvta.to.shared.u64 t, %1; cvt.u32.u64 %0, t; }" : "=r"(a) : "l"(p));
    return a;
}
__device__ __forceinline__ void cp16(uint32_t dst, const void* src) {
    asm volatile("cp.async.cg.shared.global [%0], [%1], 16;\n" :: "r"(dst), "l"(src));
}
__device__ __forceinline__ void hmma(float* c, const uint32_t* a, const uint32_t* b) {
    asm volatile(
        "mma.sync.aligned.m16n8k16.row.col.f32.bf16.bf16.f32 "
        "{%0,%1,%2,%3}, {%4,%5,%6,%7}, {%8,%9}, {%0,%1,%2,%3};"
        : "+f"(c[0]), "+f"(c[1]), "+f"(c[2]), "+f"(c[3])
        : "r"(a[0]), "r"(a[1]), "r"(a[2]), "r"(a[3]), "r"(b[0]), "r"(b[1]));
}
__device__ __forceinline__ void ldm4(uint32_t* r, uint32_t a) {
    asm volatile("ldmatrix.sync.aligned.m8n8.x4.shared.b16 {%0,%1,%2,%3}, [%4];"
        : "=r"(r[0]), "=r"(r[1]), "=r"(r[2]), "=r"(r[3]) : "r"(a));
}
__device__ __forceinline__ void ldm4t(uint32_t* r, uint32_t a) {
    asm volatile("ldmatrix.sync.aligned.m8n8.x4.trans.shared.b16 {%0,%1,%2,%3}, [%4];"
        : "=r"(r[0]), "=r"(r[1]), "=r"(r[2]), "=r"(r[3]) : "r"(a));
}
__device__ __forceinline__ uint32_t pack_split(float v0, float v1, uint32_t& lopack) {
    __nv_bfloat16 h0 = __float2bfloat16_rn(v0), h1 = __float2bfloat16_rn(v1);
    __nv_bfloat16 l0 = __float2bfloat16_rn(v0 - __bfloat162float(h0));
    __nv_bfloat16 l1 = __float2bfloat16_rn(v1 - __bfloat162float(h1));
    lopack = (uint32_t)*(unsigned short*)&l0 | ((uint32_t)*(unsigned short*)&l1 << 16);
    return (uint32_t)*(unsigned short*)&h0 | ((uint32_t)*(unsigned short*)&h1 << 16);
}

// ---------------- split fp32 -> bf16 hi/lo ----------------
__global__ __launch_bounds__(256) void split_kernel(
    const float* __restrict__ src, __nv_bfloat16* __restrict__ hi,
    __nv_bfloat16* __restrict__ lo, int n)
{
    int i = (blockIdx.x * 256 + threadIdx.x) * 4;
    if (i >= n) return;
    float4 v = *(const float4*)(src + i);
    float f[4] = {v.x, v.y, v.z, v.w};
    uint32_t lp0, lp1;
    uint32_t hp0 = pack_split(f[0], f[1], lp0);
    uint32_t hp1 = pack_split(f[2], f[3], lp1);
    uint2 hp = make_uint2(hp0, hp1), lp = make_uint2(lp0, lp1);
    *(uint2*)(hi + i) = hp; *(uint2*)(lo + i) = lp;
}

// ---------------------------------------------------------------------------
// Projection GEMM (NT, bf16x3): 128x128 CTA, 8 warps 2m x 4n, BK=32, ldmatrix.
// split_out=1 -> emit bf16 hi/lo; else f32.
// ---------------------------------------------------------------------------
#define ST_AH 0
#define ST_AL 8192
#define ST_BH 16384
#define ST_BL 24576
#define STAGE 32768
#define GEMM_SMEM 65536
#define NCH (KDIM / 32)

__global__ __launch_bounds__(256) void gemm_proj(
    const __nv_bfloat16* __restrict__ Ahp, const __nv_bfloat16* __restrict__ Alp,
    const __nv_bfloat16* __restrict__ Bhp, const __nv_bfloat16* __restrict__ Blp,
    const float* __restrict__ bias, float* __restrict__ Cf,
    __nv_bfloat16* __restrict__ Oh, __nv_bfloat16* __restrict__ Ol,
    float alpha, int split_out)
{
    const uint32_t sb = smem_u32(dynsmem);
    const int tid = threadIdx.x, wid = tid >> 5, lane = tid & 31;
    const int gid = lane >> 2, tig = lane & 3;
    const int q = lane >> 3, r8 = lane & 7, qlo = q & 1, qhi = q >> 1;
    const int wm = (wid & 1) * 64, wn = (wid >> 1) * 32;
    const int m0 = blockIdx.y * 128, n0 = blockIdx.x * 128;

    int aoff[4], axor[4], boff[2], bxor[2];
#pragma unroll
    for (int mt = 0; mt < 4; mt++) {
        int rr = wm + mt * 16 + qlo * 8 + r8;
        aoff[mt] = rr * 64; axor[mt] = (rr >> 1) & 3;
    }
#pragma unroll
    for (int p = 0; p < 2; p++) {
        int rr = wn + p * 16 + qlo * 8 + r8;
        boff[p] = rr * 64; bxor[p] = (rr >> 1) & 3;
    }

    float acc[4][4][4];
#pragma unroll
    for (int mt = 0; mt < 4; mt++)
#pragma unroll
        for (int nt = 0; nt < 4; nt++)
#pragma unroll
            for (int e = 0; e < 4; e++) acc[mt][nt][e] = 0.0f;

    auto load_chunk = [&](int c) {
        const uint32_t stg = sb + (uint32_t)(c & 1) * STAGE;
        const int k0 = c * 32;
#pragma unroll
        for (int t = 0; t < 8; t++) {
            int task = tid + t * 256;
            int isB = task >> 10, rem = task & 1023;
            int s = rem >> 9, r2 = rem & 511;
            int row = r2 >> 2, g = r2 & 3;
            uint32_t so = (uint32_t)(row * 64 + ((g ^ ((row >> 1) & 3)) << 4));
            const __nv_bfloat16* src;
            uint32_t dst;
            if (!isB) {
                src = (s ? Alp : Ahp) + (size_t)(m0 + row) * KDIM + k0 + g * 8;
                dst = stg + (s ? ST_AL : ST_AH) + so;
            } else {
                src = (s ? Blp : Bhp) + (size_t)(n0 + row) * KDIM + k0 + g * 8;
                dst = stg + (s ? ST_BL : ST_BH) + so;
            }
            cp16(dst, src);
        }
        asm volatile("cp.async.commit_group;\n" ::: "memory");
    };

    load_chunk(0); load_chunk(1);

    for (int c = 0; c < NCH; c++) {
        const uint32_t stg = sb + (uint32_t)(c & 1) * STAGE;
        if (c == NCH - 1) asm volatile("cp.async.wait_group 0;\n" ::: "memory");
        else              asm volatile("cp.async.wait_group 1;\n" ::: "memory");
        __syncthreads();
#pragma unroll
        for (int ks = 0; ks < 2; ks++) {
            const int g = ks * 2 + qhi;
            uint32_t a[4][4], b[4][2], b2[4][2], t[4];
#pragma unroll
            for (int mt = 0; mt < 4; mt++)
                ldm4(a[mt], stg + ST_AH + aoff[mt] + (uint32_t)((g ^ axor[mt]) << 4));
#pragma unroll
            for (int p = 0; p < 2; p++) {
                ldm4(t, stg + ST_BH + boff[p] + (uint32_t)((g ^ bxor[p]) << 4));
                b[2*p][0] = t[0]; b[2*p+1][0] = t[1]; b[2*p][1] = t[2]; b[2*p+1][1] = t[3];
            }
#pragma unroll
            for (int mt = 0; mt < 4; mt++)
#pragma unroll
                for (int nt = 0; nt < 4; nt++) hmma(acc[mt][nt], a[mt], b[nt]);
#pragma unroll
            for (int p = 0; p < 2; p++) {
                ldm4(t, stg + ST_BL + boff[p] + (uint32_t)((g ^ bxor[p]) << 4));
                b2[2*p][0] = t[0]; b2[2*p+1][0] = t[1]; b2[2*p][1] = t[2]; b2[2*p+1][1] = t[3];
            }
#pragma unroll
            for (int mt = 0; mt < 4; mt++)
#pragma unroll
                for (int nt = 0; nt < 4; nt++) hmma(acc[mt][nt], a[mt], b2[nt]);
#pragma unroll
            for (int mt = 0; mt < 4; mt++)
                ldm4(a[mt], stg + ST_AL + aoff[mt] + (uint32_t)((g ^ axor[mt]) << 4));
#pragma unroll
            for (int mt = 0; mt < 4; mt++)
#pragma unroll
                for (int nt = 0; nt < 4; nt++) hmma(acc[mt][nt], a[mt], b[nt]);
        }
        __syncthreads();
        if (c + 2 < NCH) load_chunk(c + 2);
    }

#pragma unroll
    for (int mt = 0; mt < 4; mt++) {
        const int row = m0 + wm + mt * 16 + gid;
#pragma unroll
        for (int nt = 0; nt < 4; nt++) {
            const int col = n0 + wn + nt * 8 + tig * 2;
            const float bb0 = __ldg(bias + col), bb1 = __ldg(bias + col + 1);
            float v0 = alpha * (acc[mt][nt][0] + bb0);
            float v1 = alpha * (acc[mt][nt][1] + bb1);
            float v2 = alpha * (acc[mt][nt][2] + bb0);
            float v3 = alpha * (acc[mt][nt][3] + bb1);
            if (split_out) {
                uint32_t lp0, lp1;
                uint32_t hp0 = pack_split(v0, v1, lp0);
                uint32_t hp1 = pack_split(v2, v3, lp1);
                size_t i0b = (size_t)row * E_DIM + col;
                size_t i1b = (size_t)(row + 8) * E_DIM + col;
                *(uint32_t*)(Oh + i0b) = hp0; *(uint32_t*)(Ol + i0b) = lp0;
                *(uint32_t*)(Oh + i1b) = hp1; *(uint32_t*)(Ol + i1b) = lp1;
            } else {
                *(float2*)(Cf + (size_t)row * E_DIM + col)      = make_float2(v0, v1);
                *(float2*)(Cf + (size_t)(row + 8) * E_DIM + col) = make_float2(v2, v3);
            }
        }
    }
}

// ---------------------------------------------------------------------------
// Scores HMMA: Wpart[z][i][j] = sum_{r in range(z), d} Q*K. z = h*8+rs.
// CTA 128x128(i,j), BK=64 (one r per chunk), 32 r per CTA.
// ---------------------------------------------------------------------------
#define SC_AH 0
#define SC_AL 16384
#define SC_BH 32768
#define SC_BL 49152
#define SC_STAGE 65536
#define SC_SMEM 131072

__global__ __launch_bounds__(256) void scores_hmma(
    const __nv_bfloat16* __restrict__ Qh, const __nv_bfloat16* __restrict__ Ql,
    const __nv_bfloat16* __restrict__ Kh, const __nv_bfloat16* __restrict__ Kl,
    float* __restrict__ Wp)
{
    const uint32_t sb = smem_u32(dynsmem);
    const int tid = threadIdx.x, wid = tid >> 5, lane = tid & 31;
    const int gid = lane >> 2, tig = lane & 3;
    const int q = lane >> 3, r8 = lane & 7, qlo = q & 1, qhi = q >> 1;
    const int wm = (wid & 1) * 64, wn = (wid >> 1) * 32;
    const int h = blockIdx.z >> 3, rs = blockIdx.z & 7;
    const int i0 = blockIdx.x * 128, j0 = blockIdx.y * 128;
    const int r_lo = rs * 32;

    int aoff[4], axor[4], boff[2], bxor[2];
#pragma unroll
    for (int mt = 0; mt < 4; mt++) {
        int rr = wm + mt * 16 + qlo * 8 + r8;
        aoff[mt] = rr * 128; axor[mt] = rr & 7;
    }
#pragma unroll
    for (int p = 0; p < 2; p++) {
        int rr = wn + p * 16 + qlo * 8 + r8;
        boff[p] = rr * 128; bxor[p] = rr & 7;
    }

    float acc[4][4][4];
#pragma unroll
    for (int mt = 0; mt < 4; mt++)
#pragma unroll
        for (int nt = 0; nt < 4; nt++)
#pragma unroll
            for (int e = 0; e < 4; e++) acc[mt][nt][e] = 0.0f;

    auto load_chunk = [&](int c) {
        const uint32_t stg = sb + (uint32_t)(c & 1) * SC_STAGE;
        const int r = r_lo + c;
#pragma unroll
        for (int t = 0; t < 16; t++) {
            int task = tid + t * 256;
            int isB = task >> 11, rem = task & 2047;
            int s = rem >> 10, r2 = rem & 1023;
            int row = r2 >> 3, g = r2 & 7;
            uint32_t so = (uint32_t)(row * 128 + ((g ^ (row & 7)) << 4));
            const __nv_bfloat16* src;
            uint32_t dst;
            if (!isB) {
                src = (s ? Ql : Qh) + (size_t)(r * 256 + i0 + row) * E_DIM + h * DH + g * 8;
                dst = stg + (s ? SC_AL : SC_AH) + so;
            } else {
                src = (s ? Kl : Kh) + (size_t)(r * 256 + j0 + row) * E_DIM + h * DH + g * 8;
                dst = stg + (s ? SC_BL : SC_BH) + so;
            }
            cp16(dst, src);
        }
        asm volatile("cp.async.commit_group;\n" ::: "memory");
    };

    load_chunk(0); load_chunk(1);

    for (int c = 0; c < 32; c++) {
        const uint32_t stg = sb + (uint32_t)(c & 1) * SC_STAGE;
        if (c == 31) asm volatile("cp.async.wait_group 0;\n" ::: "memory");
        else         asm volatile("cp.async.wait_group 1;\n" ::: "memory");
        __syncthreads();
#pragma unroll
        for (int ks = 0; ks < 4; ks++) {
            const int g = ks * 2 + qhi;
            uint32_t a[4][4], b[4][2], b2[4][2], t[4];
#pragma unroll
            for (int mt = 0; mt < 4; mt++)
                ldm4(a[mt], stg + SC_AH + aoff[mt] + (uint32_t)((g ^ axor[mt]) << 4));
#pragma unroll
            for (int p = 0; p < 2; p++) {
                ldm4(t, stg + SC_BH + boff[p] + (uint32_t)((g ^ bxor[p]) << 4));
                b[2*p][0] = t[0]; b[2*p+1][0] = t[1]; b[2*p][1] = t[2]; b[2*p+1][1] = t[3];
            }
#pragma unroll
            for (int mt = 0; mt < 4; mt++)
#pragma unroll
                for (int nt = 0; nt < 4; nt++) hmma(acc[mt][nt], a[mt], b[nt]);
#pragma unroll
            for (int p = 0; p < 2; p++) {
                ldm4(t, stg + SC_BL + boff[p] + (uint32_t)((g ^ bxor[p]) << 4));
                b2[2*p][0] = t[0]; b2[2*p+1][0] = t[1]; b2[2*p][1] = t[2]; b2[2*p+1][1] = t[3];
            }
#pragma unroll
            for (int mt = 0; mt < 4; mt++)
#pragma unroll
                for (int nt = 0; nt < 4; nt++) hmma(acc[mt][nt], a[mt], b2[nt]);
#pragma unroll
            for (int mt = 0; mt < 4; mt++)
                ldm4(a[mt], stg + SC_AL + aoff[mt] + (uint32_t)((g ^ axor[mt]) << 4));
#pragma unroll
            for (int mt = 0; mt < 4; mt++)
#pragma unroll
                for (int nt = 0; nt < 4; nt++) hmma(acc[mt][nt], a[mt], b[nt]);
        }
        __syncthreads();
        if (c + 2 < 32) load_chunk(c + 2);
    }

    float* base = Wp + (size_t)blockIdx.z * 65536;
#pragma unroll
    for (int mt = 0; mt < 4; mt++) {
        const int i = i0 + wm + mt * 16 + gid;
#pragma unroll
        for (int nt = 0; nt < 4; nt++) {
            const int j = j0 + wn + nt * 8 + tig * 2;
            *(float2*)(base + (size_t)i * 256 + j)       = make_float2(acc[mt][nt][0], acc[mt][nt][1]);
            *(float2*)(base + (size_t)(i + 8) * 256 + j) = make_float2(acc[mt][nt][2], acc[mt][nt][3]);
        }
    }
}

// ---------------------------------------------------------------------------
// Reduce partials + softmax; emit f32 probs to out AND bf16 hi/lo split.
// ---------------------------------------------------------------------------
__global__ __launch_bounds__(256) void softmax_reduce(
    const float* __restrict__ Wp, float* __restrict__ P,
    __nv_bfloat16* __restrict__ Ph, __nv_bfloat16* __restrict__ Pl)
{
    __shared__ float red[8];
    const int row = blockIdx.x;             // h*256 + i
    const int h = row >> 8;
    const int tid = threadIdx.x;

    float v = 0.0f;
#pragma unroll
    for (int rs = 0; rs < 8; rs++)
        v += Wp[((size_t)(h * 8 + rs)) * 65536 + (size_t)(row & 255) * 256 + tid];

    float m = v;
#pragma unroll
    for (int o = 16; o > 0; o >>= 1) m = fmaxf(m, __shfl_xor_sync(0xffffffffu, m, o));
    if ((tid & 31) == 0) red[tid >> 5] = m;
    __syncthreads();
    float m_all = red[0];
#pragma unroll
    for (int w = 1; w < 8; w++) m_all = fmaxf(m_all, red[w]);
    const float e = __expf(v - m_all);
    float s = e;
#pragma unroll
    for (int o = 16; o > 0; o >>= 1) s += __shfl_xor_sync(0xffffffffu, s, o);
    __syncthreads();
    if ((tid & 31) == 0) red[tid >> 5] = s;
    __syncthreads();
    float s_all = 0.0f;
#pragma unroll
    for (int w = 0; w < 8; w++) s_all += red[w];

    const float p = e / s_all;
    const size_t idx = (size_t)row * 256 + tid;
    P[idx] = p;
    __nv_bfloat16 hb = __float2bfloat16_rn(p);
    Ph[idx] = hb;
    Pl[idx] = __float2bfloat16_rn(p - __bfloat162float(hb));
}

// ---------------------------------------------------------------------------
// Context HMMA: Ctx[(r,i),(h,d)] = sum_j P[h,i,j] V[(r,j),(h,d)].
// grid (2 i-tiles, 256 r, 12 h). CTA 128(i) x 64(d), K=256(j), BK=32.
// A = P (normal ldmatrix), B = V via ldmatrix.trans. Output: bf16 hi/lo split.
// ---------------------------------------------------------------------------
#define CT_PH 0
#define CT_PL 8192
#define CT_VH 16384
#define CT_VL 20480
#define CT_STAGE 24576
#define CT_SMEM 49152

__global__ __launch_bounds__(256) void context_hmma(
    const __nv_bfloat16* __restrict__ Ph, const __nv_bfloat16* __restrict__ Pl,
    const __nv_bfloat16* __restrict__ Vh, const __nv_bfloat16* __restrict__ Vl,
    __nv_bfloat16* __restrict__ Oh, __nv_bfloat16* __restrict__ Ol)
{
    const uint32_t sb = smem_u32(dynsmem);
    const int tid = threadIdx.x, wid = tid >> 5, lane = tid & 31;
    const int gid = lane >> 2, tig = lane & 3;
    const int q = lane >> 3, r8 = lane & 7, qlo = q & 1, qhi = q >> 1;
    const int wmi = (wid >> 1) * 32, wnd = (wid & 1) * 32;
    const int i0 = blockIdx.x * 128, r = blockIdx.y, h = blockIdx.z;

    int aoff[2], axor[2];
#pragma unroll
    for (int mt = 0; mt < 2; mt++) {
        int rr = wmi + mt * 16 + qlo * 8 + r8;
        aoff[mt] = rr * 64; axor[mt] = (rr >> 1) & 3;
    }
    int gB[2];
#pragma unroll
    for (int p = 0; p < 2; p++) gB[p] = (wnd >> 3) + p * 2 + qhi;
    const int jbase = qlo * 8 + r8;

    float acc[2][4][4];
#pragma unroll
    for (int mt = 0; mt < 2; mt++)
#pragma unroll
        for (int nt = 0; nt < 4; nt++)
#pragma unroll
            for (int e = 0; e < 4; e++) acc[mt][nt][e] = 0.0f;

    auto load_chunk = [&](int c) {
        const uint32_t stg = sb + (uint32_t)(c & 1) * CT_STAGE;
        const int j0 = c * 32;
#pragma unroll
        for (int t = 0; t < 6; t++) {
            int task = tid + t * 256;
            if (task < 1024) {
                int s = task >> 9, r2 = task & 511;
                int row = r2 >> 2, g = r2 & 3;
                const __nv_bfloat16* src =
                    (s ? Pl : Ph) + (size_t)h * 65536 + (size_t)(i0 + row) * 256 + j0 + g * 8;
                cp16(stg + (s ? CT_PL : CT_PH) +
                         (uint32_t)(row * 64 + ((g ^ ((row >> 1) & 3)) << 4)), src);
            } else {
                int t2 = task - 1024;
                int s = t2 >> 8, r2 = t2 & 255;
                int row = r2 >> 3, g = r2 & 7;
                const __nv_bfloat16* src =
                    (s ? Vl : Vh) + (size_t)(r * 256 + j0 + row) * E_DIM + h * DH + g * 8;
                cp16(stg + (s ? CT_VL : CT_VH) +
                         (uint32_t)(row * 128 + ((g ^ (row & 7)) << 4)), src);
            }
        }
        asm volatile("cp.async.commit_group;\n" ::: "memory");
    };

    load_chunk(0); load_chunk(1);

    for (int c = 0; c < 8; c++) {
        const uint32_t stg = sb + (uint32_t)(c & 1) * CT_STAGE;
        if (c == 7) asm volatile("cp.async.wait_group 0;\n" ::: "memory");
        else        asm volatile("cp.async.wait_group 1;\n" ::: "memory");
        __syncthreads();
#pragma unroll
        for (int ks = 0; ks < 2; ks++) {
            const int ga = ks * 2 + qhi;
            const int jrow = ks * 16 + jbase;
            uint32_t a[2][4], b[4][2], b2[4][2], t[4];
#pragma unroll
            for (int mt = 0; mt < 2; mt++)
                ldm4(a[mt], stg + CT_PH + aoff[mt] + (uint32_t)((ga ^ axor[mt]) << 4));
#pragma unroll
            for (int p = 0; p < 2; p++) {
                ldm4t(t, stg + CT_VH + (uint32_t)(jrow * 128 + ((gB[p] ^ (jrow & 7)) << 4)));
                b[2*p][0] = t[0]; b[2*p][1] = t[1]; b[2*p+1][0] = t[2]; b[2*p+1][1] = t[3];
            }
#pragma unroll
            for (int mt = 0; mt < 2; mt++)
#pragma unroll
                for (int nt = 0; nt < 4; nt++) hmma(acc[mt][nt], a[mt], b[nt]);
#pragma unroll
            for (int p = 0; p < 2; p++) {
                ldm4t(t, stg + CT_VL + (uint32_t)(jrow * 128 + ((gB[p] ^ (jrow & 7)) << 4)));
                b2[2*p][0] = t[0]; b2[2*p][1] = t[1]; b2[2*p+1][0] = t[2]; b2[2*p+1][1] = t[3];
            }
#pragma unroll
            for (int mt = 0; mt < 2; mt++)
#pragma unroll
                for (int nt = 0; nt < 4; nt++) hmma(acc[mt][nt], a[mt], b2[nt]);
#pragma unroll
            for (int mt = 0; mt < 2; mt++)
                ldm4(a[mt], stg + CT_PL + aoff[mt] + (uint32_t)((ga ^ axor[mt]) << 4));
#pragma unroll
            for (int mt = 0; mt < 2; mt++)
#pragma unroll
                for (int nt = 0; nt < 4; nt++) hmma(acc[mt][nt], a[mt], b[nt]);
        }
        __syncthreads();
        if (c + 2 < 8) load_chunk(c + 2);
    }

#pragma unroll
    for (int mt = 0; mt < 2; mt++) {
        const int row_i = i0 + wmi + mt * 16 + gid;
#pragma unroll
        for (int nt = 0; nt < 4; nt++) {
            const int col = wnd + nt * 8 + tig * 2;
            uint32_t lp0, lp1;
            uint32_t hp0 = pack_split(acc[mt][nt][0], acc[mt][nt][1], lp0);
            uint32_t hp1 = pack_split(acc[mt][nt][2], acc[mt][nt][3], lp1);
            size_t i0b = (size_t)(r * 256 + row_i) * E_DIM + h * DH + col;
            size_t i1b = (size_t)(r * 256 + row_i + 8) * E_DIM + h * DH + col;
            *(uint32_t*)(Oh + i0b) = hp0; *(uint32_t*)(Ol + i0b) = lp0;
            *(uint32_t*)(Oh + i1b) = hp1; *(uint32_t*)(Ol + i1b) = lp1;
        }
    }
}

// ---------------- launch ----------------
extern "C" void kernel_launch(void* const* d_in, const int* in_sizes, int n_in,
                              void* d_out, int out_size)
{
    const float* x  = (const float*)d_in[0];
    const float* Wq = (const float*)d_in[1];
    const float* bq = (const float*)d_in[2];
    const float* Wk = (const float*)d_in[3];
    const float* bk = (const float*)d_in[4];
    const float* Wv = (const float*)d_in[5];
    const float* bv = (const float*)d_in[6];
    const float* Wo = (const float*)d_in[7];
    const float* bo = (const float*)d_in[8];

    float* out_y = (float*)d_out;
    float* out_p = (float*)d_out + PROJ_ELEMS;

    __nv_bfloat16 *Ah, *Al, *Qh, *Ql, *Kh, *Kl, *Vh, *Vl, *Wh, *Wl, *Ph, *Pl;
    float* Wp;
    cudaGetSymbolAddress((void**)&Ah, g_Ah);
    cudaGetSymbolAddress((void**)&Al, g_Al);
    cudaGetSymbolAddress((void**)&Qh, g_Qh);
    cudaGetSymbolAddress((void**)&Ql, g_Ql);
    cudaGetSymbolAddress((void**)&Kh, g_Kh);
    cudaGetSymbolAddress((void**)&Kl, g_Kl);
    cudaGetSymbolAddress((void**)&Vh, g_Vh);
    cudaGetSymbolAddress((void**)&Vl, g_Vl);
    cudaGetSymbolAddress((void**)&Wh, g_Wh);
    cudaGetSymbolAddress((void**)&Wl, g_Wl);
    cudaGetSymbolAddress((void**)&Ph, g_Ph);
    cudaGetSymbolAddress((void**)&Pl, g_Pl);
    cudaGetSymbolAddress((void**)&Wp, g_Wpart);

    cudaFuncSetAttribute(gemm_proj,    cudaFuncAttributeMaxDynamicSharedMemorySize, GEMM_SMEM);
    cudaFuncSetAttribute(scores_hmma,  cudaFuncAttributeMaxDynamicSharedMemorySize, SC_SMEM);
    cudaFuncSetAttribute(context_hmma, cudaFuncAttributeMaxDynamicSharedMemorySize, CT_SMEM);

    const int nx = (int)PROJ_ELEMS, nw = (int)WSZ;
    split_kernel<<<nx / 1024, 256>>>(x, Ah, Al, nx);
    split_kernel<<<nw / 1024, 256>>>(Wq, Wh + 0 * WSZ, Wl + 0 * WSZ, nw);
    split_kernel<<<nw / 1024, 256>>>(Wk, Wh + 1 * WSZ, Wl + 1 * WSZ, nw);
    split_kernel<<<nw / 1024, 256>>>(Wv, Wh + 2 * WSZ, Wl + 2 * WSZ, nw);
    split_kernel<<<nw / 1024, 256>>>(Wo, Wh + 3 * WSZ, Wl + 3 * WSZ, nw);

    dim3 gg(E_DIM / 128, TOK / 128);
    gemm_proj<<<gg, 256, GEMM_SMEM>>>(Ah, Al, Wh + 0 * WSZ, Wl + 0 * WSZ, bq,
                                      nullptr, Qh, Ql, SCALE, 1);
    gemm_proj<<<gg, 256, GEMM_SMEM>>>(Ah, Al, Wh + 1 * WSZ, Wl + 1 * WSZ, bk,
                                      nullptr, Kh, Kl, 1.0f, 1);
    gemm_proj<<<gg, 256, GEMM_SMEM>>>(Ah, Al, Wh + 2 * WSZ, Wl + 2 * WSZ, bv,
                                      nullptr, Vh, Vl, 1.0f, 1);

    scores_hmma<<<dim3(2, 2, 96), 256, SC_SMEM>>>(Qh, Ql, Kh, Kl, Wp);
    softmax_reduce<<<H_HEADS * C_DIM, 256>>>(Wp, out_p, Ph, Pl);
    context_hmma<<<dim3(2, 256, 12), 256, CT_SMEM>>>(Ph, Pl, Vh, Vl, Ah, Al);

    gemm_proj<<<gg, 256, GEMM_SMEM>>>(Ah, Al, Wh + 3 * WSZ, Wl + 3 * WSZ, bo,
                                      out_y, nullptr, nullptr, 1.0f, 0);
}